// round 12
// baseline (speedup 1.0000x reference)
#include <cuda_runtime.h>
#include <math.h>
#include <stdint.h>

// ===========================================================================
// EncoderAttention3 via mma.sync tf32 (m16n8k8), register accumulators.
// R10: 512 threads/CTA with 32x32 warp tiles (16 warps over M=64xN=256),
//      2 CTAs/SM -> 8 warps/SMSP (occ ~50%). Same per-SM LDS/MMA counts as
//      R8; pure latency-hiding win. k-block LDS.128 layouts from R8.
// ===========================================================================

namespace {
constexpr int OBS_DIM = 216, EGO = 48, NEIGH = 7, H = 256, DOUT = 64, OUT_DIM = 112;
constexpr int BATCHES = 16384;
constexpr int BPB     = 8;
constexpr int RVALID  = BPB * NEIGH;   // 56
constexpr int M       = 64;
constexpr int K1      = 80;            // padded 73 -> 80 (5 chunks of 16)
constexpr int THREADS = 512;
constexpr int CH      = 16;
constexpr int NC1     = K1 / CH;       // 5
constexpr int NC2     = H / CH;        // 16
constexpr int NCHUNK  = NC1 + NC2;     // 21
constexpr int XS      = 80;            // X row stride  (320 B; mod 128 == 64)
constexpr int H1S     = 272;           // h1 row stride (1088 B; mod 128 == 64)
constexpr int BUFSZ   = CH * H;        // 4096 floats per 16-k weight chunk [n][16]

// smem layout (float offsets)
constexpr int B1C = 0;                 // 256
constexpr int GC  = 256;               // 256
constexpr int BBC = 512;               // 256
constexpr int B2C = 768;               // 256
constexpr int B3C = 1024;              // 64
constexpr int PSU = 1088;              // [8][64]
constexpr int PSQ = 1600;              // [8][64]
constexpr int H1O = 2112;              // h1 [64][272]  (X [64][80] aliases this)
constexpr int XO  = H1O;
constexpr int BUF = H1O + M * H1S;     // 19520 (128B aligned): 2 chunk buffers
constexpr int SSO = BUF;               // ss [8][256] aliases dead weight buffers
constexpr int SMEM_FLOATS = BUF + 2 * BUFSZ;   // 27712
constexpr int SMEM_BYTES  = SMEM_FLOATS * 4;   // 110848 (2 CTAs/SM)
}  // namespace

// weight chunk images, 16-float k-block layout:
//   chunk[n][pos], pos = 4*lr + 2*ks + hh  ->  k = chunk*16 + ks*8 + lr + 4*hh
__device__ float g_w1[NC1 * BUFSZ];
__device__ float g_w2[NC2 * BUFSZ];

// ---------------------------------------------------------------------------
__device__ __forceinline__ uint32_t tf32r(float f) {
    uint32_t u;
    asm("cvt.rna.tf32.f32 %0, %1;" : "=r"(u) : "f"(f));
    return u;
}
__device__ __forceinline__ float tanha(float x) {
    float y;
    asm("tanh.approx.f32 %0, %1;" : "=f"(y) : "f"(x));
    return y;
}
__device__ __forceinline__ void cp16(uint32_t dst, const void* src) {
    asm volatile("cp.async.cg.shared.global [%0], [%1], 16;" :: "r"(dst), "l"(src));
}
#define CP_COMMIT() asm volatile("cp.async.commit_group;" ::: "memory")
#define CP_WAIT0()  asm volatile("cp.async.wait_group 0;" ::: "memory")

__device__ __forceinline__ void mma8(float d[4], const uint32_t a[4],
                                     uint32_t b0, uint32_t b1) {
    asm volatile("mma.sync.aligned.m16n8k8.row.col.f32.tf32.tf32.f32 "
                 "{%0,%1,%2,%3},{%4,%5,%6,%7},{%8,%9},{%0,%1,%2,%3};"
                 : "+f"(d[0]), "+f"(d[1]), "+f"(d[2]), "+f"(d[3])
                 : "r"(a[0]), "r"(a[1]), "r"(a[2]), "r"(a[3]), "r"(b0), "r"(b1));
}

// logical k-in-block (0..15) -> physical position in the 16-float block
__device__ __forceinline__ int kpos(int km) {
    return 4 * (km & 3) + 2 * (km >> 3) + ((km >> 2) & 1);
}

// one 16-k chunk, 32x32 warp tile, all LDS.128:
//   A rows [64][as], phys cols k-blocked; B chunk [256 n][16]
__device__ __forceinline__ void gemm_chunk16(const float* __restrict__ A, int as, int k0,
                                             const float* __restrict__ B,
                                             float d[2][4][4], int rb, int cb,
                                             int lq, int lr) {
    uint32_t a[2][2][4];   // [t][ks][frag]
#pragma unroll
    for (int t = 0; t < 2; ++t) {
        const float* ap = A + (rb + t * 16 + lq) * as + k0 + 4 * lr;
        const float4 v0 = *(const float4*)ap;             // row lq
        const float4 v1 = *(const float4*)(ap + 8 * as);  // row lq+8
        a[t][0][0] = __float_as_uint(v0.x); a[t][0][1] = __float_as_uint(v1.x);
        a[t][0][2] = __float_as_uint(v0.y); a[t][0][3] = __float_as_uint(v1.y);
        a[t][1][0] = __float_as_uint(v0.z); a[t][1][1] = __float_as_uint(v1.z);
        a[t][1][2] = __float_as_uint(v0.w); a[t][1][3] = __float_as_uint(v1.w);
    }
    const float* bb = B + (cb + lq) * 16 + lr * 4;
#pragma unroll
    for (int j = 0; j < 4; ++j) {
        const float4 bv = *(const float4*)(bb + j * 128);
        const uint32_t b00 = __float_as_uint(bv.x), b01 = __float_as_uint(bv.y);
        const uint32_t b10 = __float_as_uint(bv.z), b11 = __float_as_uint(bv.w);
        mma8(d[0][j], a[0][0], b00, b01);
        mma8(d[1][j], a[1][0], b00, b01);
        mma8(d[0][j], a[0][1], b10, b11);
        mma8(d[1][j], a[1][1], b10, b11);
    }
}

// ---------------------------------------------------------------------------
__global__ void prep_kernel(const float* __restrict__ W1, const float* __restrict__ W2) {
    const int idx = blockIdx.x * blockDim.x + threadIdx.x;
    const int T1 = NC1 * BUFSZ;
    if (idx < T1 + NC2 * BUFSZ) {
        const bool w1 = idx < T1;
        const int i2 = w1 ? idx : idx - T1;
        const int chunk = i2 / BUFSZ;
        const int rem   = i2 - chunk * BUFSZ;
        const int n   = rem >> 4;
        const int pos = rem & 15;
        const int lr = pos >> 2, ks = (pos >> 1) & 1, hh = pos & 1;
        const int k  = chunk * CH + ks * 8 + lr + 4 * hh;
        float v = 0.0f;
        if (w1) { if (k < 73) v = W1[k * H + n]; }
        else                  v = W2[k * H + n];
        (w1 ? g_w1 : g_w2)[i2] = __uint_as_float(tf32r(v));
    }
}

// ---------------------------------------------------------------------------
__global__ void __launch_bounds__(THREADS, 2)
enc3_mma_kernel(const float* __restrict__ obs,
                const float* __restrict__ b1, const float* __restrict__ ln_g,
                const float* __restrict__ ln_b, const float* __restrict__ b2,
                const float* __restrict__ W3, const float* __restrict__ b3,
                float* __restrict__ out)
{
    extern __shared__ float sm[];
    const int tid  = threadIdx.x;
    const int wid  = tid >> 5;
    const int lane = tid & 31;
    const int lq   = lane >> 2, lr = lane & 3;
    const int rb   = (wid >> 3) * 32;    // 2 row groups of 32 rows
    const int cb   = (wid & 7) * 32;     // 8 col groups of 32 cols
    const int b0   = blockIdx.x * BPB;
    const uint32_t smu = (uint32_t)__cvta_generic_to_shared(sm);

    // ---- group0: chunk 0 + const vectors ------------------------------------
    {
        const uint32_t dst = smu + BUF * 4;
        for (int i = tid; i < BUFSZ / 4; i += THREADS)
            cp16(dst + i * 16, (const float4*)g_w1 + i);
        if (tid < 64)        cp16(smu + B1C * 4 + tid * 16, (const float4*)b1 + tid);
        else if (tid < 128)  cp16(smu + GC  * 4 + (tid - 64) * 16, (const float4*)ln_g + (tid - 64));
        else if (tid < 192)  cp16(smu + BBC * 4 + (tid - 128) * 16, (const float4*)ln_b + (tid - 128));
        else if (tid < 256)  cp16(smu + B2C * 4 + (tid - 192) * 16, (const float4*)b2 + (tid - 192));
        else if (tid < 272)  cp16(smu + B3C * 4 + (tid - 256) * 16, (const float4*)b3 + (tid - 256));
        CP_COMMIT();
    }

    // ---- assemble X (tf32, k-block layout) + ego passthrough ----------------
    for (int i = tid; i < M * K1; i += THREADS) {
        const int r = i / K1, c = i - r * K1;
        float v = 0.0f;
        if (r < RVALID && c < 73) {
            const int bl = r / NEIGH, n = r - bl * NEIGH;
            const float* ob = obs + (size_t)(b0 + bl) * OBS_DIM;
            if (c < EGO)      v = ob[c];
            else if (c < 72)  v = ob[EGO + (c - EGO) * NEIGH + n];
            else              v = (n >= 3) ? 1.0f : 0.0f;
        }
        const int phys = (c & ~15) + kpos(c & 15);
        sm[XO + r * XS + phys] = __uint_as_float(tf32r(v));
    }
    for (int i = tid; i < BPB * EGO; i += THREADS) {
        const int bb = i / EGO, f = i - bb * EGO;
        out[(size_t)(b0 + bb) * OUT_DIM + f] = obs[(size_t)(b0 + bb) * OBS_DIM + f];
    }

    float d[2][4][4];
#pragma unroll
    for (int t = 0; t < 2; ++t)
#pragma unroll
        for (int j = 0; j < 4; ++j)
#pragma unroll
            for (int e = 0; e < 4; ++e) d[t][j][e] = 0.0f;

    // ---- GEMM1: chunks 0..NC1-1 (1 barrier per chunk) -----------------------
    for (int c = 0; c < NC1; ++c) {
        CP_WAIT0();
        __syncthreads();
        {   // issue chunk c+1 into the buffer freed by chunk c-1
            const int nc = c + 1;
            const float* gsrc = (nc < NC1) ? (g_w1 + nc * BUFSZ) : (g_w2 + (nc - NC1) * BUFSZ);
            const uint32_t dst = smu + (BUF + (nc & 1) * BUFSZ) * 4;
            for (int i = tid; i < BUFSZ / 4; i += THREADS)
                cp16(dst + i * 16, (const float4*)gsrc + i);
            CP_COMMIT();
        }
        gemm_chunk16(sm + XO, XS, c * CH, sm + BUF + (c & 1) * BUFSZ, d, rb, cb, lq, lr);
    }

    // ---- epilogue 1: +b1, LayerNorm, tanh -> h1 (tf32, k-block layout) ------
    {
        float s[2][2] = {{0.f, 0.f}, {0.f, 0.f}};
        float q[2][2] = {{0.f, 0.f}, {0.f, 0.f}};
#pragma unroll
        for (int t = 0; t < 2; ++t)
#pragma unroll
            for (int j = 0; j < 4; ++j)
#pragma unroll
                for (int e = 0; e < 4; ++e) {
                    const float v = d[t][j][e] + sm[B1C + cb + j * 8 + lr * 2 + (e & 1)];
                    d[t][j][e] = v;
                    s[t][e >> 1] += v;
                    q[t][e >> 1] = fmaf(v, v, q[t][e >> 1]);
                }
#pragma unroll
        for (int t = 0; t < 2; ++t)
#pragma unroll
            for (int h = 0; h < 2; ++h)
#pragma unroll
                for (int o = 1; o < 4; o <<= 1) {
                    s[t][h] += __shfl_xor_sync(0xffffffffu, s[t][h], o);
                    q[t][h] += __shfl_xor_sync(0xffffffffu, q[t][h], o);
                }
        if (lr == 0) {
#pragma unroll
            for (int t = 0; t < 2; ++t)
#pragma unroll
                for (int h = 0; h < 2; ++h) {
                    const int r = rb + t * 16 + h * 8 + lq;
                    sm[PSU + (wid & 7) * 64 + r] = s[t][h];
                    sm[PSQ + (wid & 7) * 64 + r] = q[t][h];
                }
        }
        __syncthreads();
        float mu[2][2], rs[2][2];
#pragma unroll
        for (int t = 0; t < 2; ++t)
#pragma unroll
            for (int h = 0; h < 2; ++h) {
                const int r = rb + t * 16 + h * 8 + lq;
                float ts = 0.0f, tq = 0.0f;
#pragma unroll
                for (int p = 0; p < 8; ++p) {
                    ts += sm[PSU + p * 64 + r];
                    tq += sm[PSQ + p * 64 + r];
                }
                mu[t][h] = ts * (1.0f / 256.0f);
                const float var = fmaf(tq, 1.0f / 256.0f, -mu[t][h] * mu[t][h]);
                rs[t][h] = rsqrtf(var + 1e-5f);
            }
        __syncthreads();   // all warps done reading X before h1 overwrites region
#pragma unroll
        for (int t = 0; t < 2; ++t)
#pragma unroll
            for (int j = 0; j < 4; ++j)
#pragma unroll
                for (int e = 0; e < 4; ++e) {
                    const int h = e >> 1;
                    const int r = rb + t * 16 + h * 8 + lq;
                    const int col = cb + j * 8 + lr * 2 + (e & 1);          // logical
                    const int phys = (col & ~15) + kpos(col & 15);          // k-block
                    const float y = tanha(fmaf((d[t][j][e] - mu[t][h]) * rs[t][h],
                                               sm[GC + col], sm[BBC + col]));
                    sm[H1O + r * H1S + phys] = __uint_as_float(tf32r(y));
                    d[t][j][e] = 0.0f;
                }
    }

    // ---- GEMM2: chunks NC1..NCHUNK-1 ---------------------------------------
    for (int c = NC1; c < NCHUNK; ++c) {
        CP_WAIT0();
        __syncthreads();
        if (c + 1 < NCHUNK) {
            const float* gsrc = g_w2 + (c + 1 - NC1) * BUFSZ;
            const uint32_t dst = smu + (BUF + ((c + 1) & 1) * BUFSZ) * 4;
            for (int i = tid; i < BUFSZ / 4; i += THREADS)
                cp16(dst + i * 16, (const float4*)gsrc + i);
            CP_COMMIT();
        }
        gemm_chunk16(sm + H1O, H1S, (c - NC1) * CH, sm + BUF + (c & 1) * BUFSZ, d, rb, cb, lq, lr);
    }
    __syncthreads();   // all warps done reading h1/weights before overwrite

    // ---- epilogue 2: +b2, ELU -> h2 (logical cols, h1 region) ---------------
#pragma unroll
    for (int t = 0; t < 2; ++t)
#pragma unroll
        for (int j = 0; j < 4; ++j)
#pragma unroll
            for (int e = 0; e < 4; ++e) {
                const int h = e >> 1;
                const int r = rb + t * 16 + h * 8 + lq;
                const int col = cb + j * 8 + lr * 2 + (e & 1);
                float v = d[t][j][e] + sm[B2C + col];
                v = (v > 0.0f) ? v : (__expf(v) - 1.0f);
                sm[H1O + r * H1S + col] = v;
            }
    __syncthreads();

    // ---- neighbor-sum -> ss[8][256] (aliases dead weight buffers) -----------
    {
        const int b = tid >> 6, c0 = (tid & 63) * 4;
        float4 a0 = make_float4(0.f, 0.f, 0.f, 0.f);
        const float* base = sm + H1O + (b * NEIGH) * H1S + c0;
#pragma unroll
        for (int n = 0; n < NEIGH; ++n) {
            const float4 u0 = *(const float4*)(base + n * H1S);
            a0.x += u0.x; a0.y += u0.y; a0.z += u0.z; a0.w += u0.w;
        }
        *(float4*)(sm + SSO + b * H + c0) = a0;
    }
    __syncthreads();

    // ---- GEMM3 (SIMT, W3 via LDG/L1): latent = ss @ W3 + b3 -----------------
    {
        const int b = tid >> 6, o = tid & 63;
        const float* ssr = sm + SSO + b * H;
        float a0 = 0.0f;
#pragma unroll 8
        for (int k = 0; k < H; ++k)
            a0 = fmaf(ssr[k], __ldg(W3 + k * DOUT + o), a0);
        out[(size_t)(b0 + b) * OUT_DIM + EGO + o] = a0 + sm[B3C + o];
    }
}

extern "C" void kernel_launch(void* const* d_in, const int* in_sizes, int n_in,
                              void* d_out, int out_size)
{
    (void)in_sizes; (void)n_in; (void)out_size;
    const float* obs  = (const float*)d_in[0];
    const float* W1   = (const float*)d_in[1];
    const float* b1   = (const float*)d_in[2];
    const float* ln_g = (const float*)d_in[3];
    const float* ln_b = (const float*)d_in[4];
    const float* W2   = (const float*)d_in[5];
    const float* b2   = (const float*)d_in[6];
    const float* W3   = (const float*)d_in[7];
    const float* b3   = (const float*)d_in[8];
    float* out = (float*)d_out;

    const int prep_elems = (NC1 + NC2) * BUFSZ;
    prep_kernel<<<(prep_elems + 255) / 256, 256>>>(W1, W2);

    cudaFuncSetAttribute(enc3_mma_kernel, cudaFuncAttributeMaxDynamicSharedMemorySize, SMEM_BYTES);
    enc3_mma_kernel<<<BATCHES / BPB, THREADS, SMEM_BYTES>>>(
        obs, b1, ln_g, ln_b, b2, W3, b3, out);
}

// round 13
// speedup vs baseline: 1.2618x; 1.2618x over previous
#include <cuda_runtime.h>
#include <math.h>
#include <stdint.h>

// ===========================================================================
// EncoderAttention3 via mma.sync tf32 (m16n8k8), register accumulators.
// R11: weights fetched per-fragment via coalesced LDG.128 from pre-swizzled
//      global images (L1-resident; shared by 16 warps/SM). No smem weight
//      staging, no cp.async double buffer, no mainloop barriers. A operands
//      (X/h1) stay in smem with R8's k-block LDS.128 layout. 2 CTAs/SM.
// ===========================================================================

namespace {
constexpr int OBS_DIM = 216, EGO = 48, NEIGH = 7, H = 256, DOUT = 64, OUT_DIM = 112;
constexpr int BATCHES = 16384;
constexpr int BPB     = 8;
constexpr int RVALID  = BPB * NEIGH;   // 56
constexpr int M       = 64;
constexpr int K1      = 80;            // padded 73 -> 80 (5 chunks of 16)
constexpr int THREADS = 256;
constexpr int CH      = 16;
constexpr int NC1     = K1 / CH;       // 5
constexpr int NC2     = H / CH;        // 16
constexpr int XS      = 80;            // X row stride  (320 B; mod 128 == 64)
constexpr int H1S     = 272;           // h1 row stride (1088 B; mod 128 == 64)
constexpr int BUFSZ   = CH * H;        // 4096 floats per 16-k weight chunk [n][16]

// smem layout (float offsets)
constexpr int B1C = 0;                 // 256
constexpr int GC  = 256;               // 256
constexpr int BBC = 512;               // 256
constexpr int B2C = 768;               // 256
constexpr int B3C = 1024;              // 64
constexpr int PSU = 1088;              // [4][64]
constexpr int PSQ = 1344;              // [4][64]
constexpr int H1O = 1600;              // h1 [64][272]  (X [64][80] aliases this)
constexpr int XO  = H1O;
constexpr int SSO = H1O + M * H1S;     // 19008: ss [8][256]
constexpr int SMEM_FLOATS = SSO + BPB * H;     // 21056
constexpr int SMEM_BYTES  = SMEM_FLOATS * 4;   // 84224 (2 CTAs/SM)
}  // namespace

// weight chunk images, 16-float k-block layout:
//   chunk[n][pos], pos = 4*lr + 2*ks + hh  ->  k = chunk*16 + ks*8 + lr + 4*hh
__device__ float g_w1[NC1 * BUFSZ];
__device__ float g_w2[NC2 * BUFSZ];

// ---------------------------------------------------------------------------
__device__ __forceinline__ uint32_t tf32r(float f) {
    uint32_t u;
    asm("cvt.rna.tf32.f32 %0, %1;" : "=r"(u) : "f"(f));
    return u;
}
__device__ __forceinline__ float tanha(float x) {
    float y;
    asm("tanh.approx.f32 %0, %1;" : "=f"(y) : "f"(x));
    return y;
}
__device__ __forceinline__ void cp16(uint32_t dst, const void* src) {
    asm volatile("cp.async.cg.shared.global [%0], [%1], 16;" :: "r"(dst), "l"(src));
}
#define CP_COMMIT() asm volatile("cp.async.commit_group;" ::: "memory")
#define CP_WAIT0()  asm volatile("cp.async.wait_group 0;" ::: "memory")

__device__ __forceinline__ void mma8(float d[4], const uint32_t a[4],
                                     uint32_t b0, uint32_t b1) {
    asm volatile("mma.sync.aligned.m16n8k8.row.col.f32.tf32.tf32.f32 "
                 "{%0,%1,%2,%3},{%4,%5,%6,%7},{%8,%9},{%0,%1,%2,%3};"
                 : "+f"(d[0]), "+f"(d[1]), "+f"(d[2]), "+f"(d[3])
                 : "r"(a[0]), "r"(a[1]), "r"(a[2]), "r"(a[3]), "r"(b0), "r"(b1));
}

// logical k-in-block (0..15) -> physical position in the 16-float block
__device__ __forceinline__ int kpos(int km) {
    return 4 * (km & 3) + 2 * (km >> 3) + ((km >> 2) & 1);
}

// one 16-k chunk: A (smem, LDS.128, k-block layout), B (global, LDG.128, L1)
__device__ __forceinline__ void gemm_chunk16(const float* __restrict__ A, int as, int k0,
                                             const float4* __restrict__ Bg,
                                             float d[2][8][4], int rb, int cb,
                                             int lq, int lr) {
    uint32_t a[2][2][4];   // [t][ks][frag]
#pragma unroll
    for (int t = 0; t < 2; ++t) {
        const float* ap = A + (rb + t * 16 + lq) * as + k0 + 4 * lr;
        const float4 v0 = *(const float4*)ap;             // row lq
        const float4 v1 = *(const float4*)(ap + 8 * as);  // row lq+8
        a[t][0][0] = __float_as_uint(v0.x); a[t][0][1] = __float_as_uint(v1.x);
        a[t][0][2] = __float_as_uint(v0.y); a[t][0][3] = __float_as_uint(v1.y);
        a[t][1][0] = __float_as_uint(v0.z); a[t][1][1] = __float_as_uint(v1.z);
        a[t][1][2] = __float_as_uint(v0.w); a[t][1][3] = __float_as_uint(v1.w);
    }
    // lane (lq,lr) -> float4 index (cb+lq)*4 + lr; warp covers 512B contiguous
    const float4* bb = Bg + (cb + lq) * 4 + lr;
#pragma unroll
    for (int j = 0; j < 8; ++j) {
        const float4 bv = __ldg(bb + j * 32);   // j*8 n-rows = 32 float4s
        const uint32_t b00 = __float_as_uint(bv.x), b01 = __float_as_uint(bv.y);
        const uint32_t b10 = __float_as_uint(bv.z), b11 = __float_as_uint(bv.w);
        mma8(d[0][j], a[0][0], b00, b01);
        mma8(d[1][j], a[1][0], b00, b01);
        mma8(d[0][j], a[0][1], b10, b11);
        mma8(d[1][j], a[1][1], b10, b11);
    }
}

// ---------------------------------------------------------------------------
__global__ void prep_kernel(const float* __restrict__ W1, const float* __restrict__ W2) {
    const int idx = blockIdx.x * blockDim.x + threadIdx.x;
    const int T1 = NC1 * BUFSZ;
    if (idx < T1 + NC2 * BUFSZ) {
        const bool w1 = idx < T1;
        const int i2 = w1 ? idx : idx - T1;
        const int chunk = i2 / BUFSZ;
        const int rem   = i2 - chunk * BUFSZ;
        const int n   = rem >> 4;
        const int pos = rem & 15;
        const int lr = pos >> 2, ks = (pos >> 1) & 1, hh = pos & 1;
        const int k  = chunk * CH + ks * 8 + lr + 4 * hh;
        float v = 0.0f;
        if (w1) { if (k < 73) v = W1[k * H + n]; }
        else                  v = W2[k * H + n];
        (w1 ? g_w1 : g_w2)[i2] = __uint_as_float(tf32r(v));
    }
}

// ---------------------------------------------------------------------------
__global__ void __launch_bounds__(THREADS, 2)
enc3_mma_kernel(const float* __restrict__ obs,
                const float* __restrict__ b1, const float* __restrict__ ln_g,
                const float* __restrict__ ln_b, const float* __restrict__ b2,
                const float* __restrict__ W3, const float* __restrict__ b3,
                float* __restrict__ out)
{
    extern __shared__ float sm[];
    const int tid  = threadIdx.x;
    const int wid  = tid >> 5;
    const int lane = tid & 31;
    const int lq   = lane >> 2, lr = lane & 3;
    const int rb   = (wid >> 2) * 32;    // 2 row groups of 32 rows
    const int cb   = (wid & 3) * 64;     // 4 col groups of 64 cols
    const int b0   = blockIdx.x * BPB;
    const uint32_t smu = (uint32_t)__cvta_generic_to_shared(sm);

    // ---- const vectors via cp.async ----------------------------------------
    {
        if (tid < 64)        cp16(smu + B1C * 4 + tid * 16, (const float4*)b1 + tid);
        else if (tid < 128)  cp16(smu + GC  * 4 + (tid - 64) * 16, (const float4*)ln_g + (tid - 64));
        else if (tid < 192)  cp16(smu + BBC * 4 + (tid - 128) * 16, (const float4*)ln_b + (tid - 128));
        else                 cp16(smu + B2C * 4 + (tid - 192) * 16, (const float4*)b2 + (tid - 192));
        if (tid < 16)        cp16(smu + B3C * 4 + tid * 16, (const float4*)b3 + tid);
        CP_COMMIT();
    }

    // ---- assemble X (tf32, k-block layout) + ego passthrough ----------------
    for (int i = tid; i < M * K1; i += THREADS) {
        const int r = i / K1, c = i - r * K1;
        float v = 0.0f;
        if (r < RVALID && c < 73) {
            const int bl = r / NEIGH, n = r - bl * NEIGH;
            const float* ob = obs + (size_t)(b0 + bl) * OBS_DIM;
            if (c < EGO)      v = ob[c];
            else if (c < 72)  v = ob[EGO + (c - EGO) * NEIGH + n];
            else              v = (n >= 3) ? 1.0f : 0.0f;
        }
        const int phys = (c & ~15) + kpos(c & 15);
        sm[XO + r * XS + phys] = __uint_as_float(tf32r(v));
    }
    for (int i = tid; i < BPB * EGO; i += THREADS) {
        const int bb = i / EGO, f = i - bb * EGO;
        out[(size_t)(b0 + bb) * OUT_DIM + f] = obs[(size_t)(b0 + bb) * OBS_DIM + f];
    }

    CP_WAIT0();
    __syncthreads();   // X + consts visible block-wide

    float d[2][8][4];
#pragma unroll
    for (int t = 0; t < 2; ++t)
#pragma unroll
        for (int j = 0; j < 8; ++j)
#pragma unroll
            for (int e = 0; e < 4; ++e) d[t][j][e] = 0.0f;

    // ---- GEMM1: 5 chunks, no barriers (B via LDG/L1) ------------------------
#pragma unroll
    for (int c = 0; c < NC1; ++c)
        gemm_chunk16(sm + XO, XS, c * CH, (const float4*)(g_w1 + c * BUFSZ),
                     d, rb, cb, lq, lr);

    // ---- epilogue 1: +b1, LayerNorm, tanh -> h1 (tf32, k-block layout) ------
    {
        float s[2][2] = {{0.f, 0.f}, {0.f, 0.f}};
        float q[2][2] = {{0.f, 0.f}, {0.f, 0.f}};
#pragma unroll
        for (int t = 0; t < 2; ++t)
#pragma unroll
            for (int j = 0; j < 8; ++j)
#pragma unroll
                for (int e = 0; e < 4; ++e) {
                    const float v = d[t][j][e] + sm[B1C + cb + j * 8 + lr * 2 + (e & 1)];
                    d[t][j][e] = v;
                    s[t][e >> 1] += v;
                    q[t][e >> 1] = fmaf(v, v, q[t][e >> 1]);
                }
#pragma unroll
        for (int t = 0; t < 2; ++t)
#pragma unroll
            for (int h = 0; h < 2; ++h)
#pragma unroll
                for (int o = 1; o < 4; o <<= 1) {
                    s[t][h] += __shfl_xor_sync(0xffffffffu, s[t][h], o);
                    q[t][h] += __shfl_xor_sync(0xffffffffu, q[t][h], o);
                }
        if (lr == 0) {
#pragma unroll
            for (int t = 0; t < 2; ++t)
#pragma unroll
                for (int h = 0; h < 2; ++h) {
                    const int r = rb + t * 16 + h * 8 + lq;
                    sm[PSU + (wid & 3) * 64 + r] = s[t][h];
                    sm[PSQ + (wid & 3) * 64 + r] = q[t][h];
                }
        }
        __syncthreads();
        float mu[2][2], rs[2][2];
#pragma unroll
        for (int t = 0; t < 2; ++t)
#pragma unroll
            for (int h = 0; h < 2; ++h) {
                const int r = rb + t * 16 + h * 8 + lq;
                const float ts = sm[PSU + r] + sm[PSU + 64 + r] + sm[PSU + 128 + r] + sm[PSU + 192 + r];
                const float tq = sm[PSQ + r] + sm[PSQ + 64 + r] + sm[PSQ + 128 + r] + sm[PSQ + 192 + r];
                mu[t][h] = ts * (1.0f / 256.0f);
                const float var = fmaf(tq, 1.0f / 256.0f, -mu[t][h] * mu[t][h]);
                rs[t][h] = rsqrtf(var + 1e-5f);
            }
        __syncthreads();   // all warps done reading X before h1 overwrites region
#pragma unroll
        for (int t = 0; t < 2; ++t)
#pragma unroll
            for (int j = 0; j < 8; ++j)
#pragma unroll
                for (int e = 0; e < 4; ++e) {
                    const int h = e >> 1;
                    const int r = rb + t * 16 + h * 8 + lq;
                    const int col = cb + j * 8 + lr * 2 + (e & 1);          // logical
                    const int phys = (col & ~15) + kpos(col & 15);          // k-block
                    const float y = tanha(fmaf((d[t][j][e] - mu[t][h]) * rs[t][h],
                                               sm[GC + col], sm[BBC + col]));
                    sm[H1O + r * H1S + phys] = __uint_as_float(tf32r(y));
                    d[t][j][e] = 0.0f;
                }
    }
    __syncthreads();   // h1 visible block-wide before GEMM2

    // ---- GEMM2: 16 chunks, no barriers (B via LDG/L1) -----------------------
#pragma unroll 4
    for (int c = 0; c < NC2; ++c)
        gemm_chunk16(sm + H1O, H1S, c * CH, (const float4*)(g_w2 + c * BUFSZ),
                     d, rb, cb, lq, lr);
    __syncthreads();   // all warps done reading h1 before epilogue 2 overwrites

    // ---- epilogue 2: +b2, ELU -> h2 (logical cols, h1 region) ---------------
#pragma unroll
    for (int t = 0; t < 2; ++t)
#pragma unroll
        for (int j = 0; j < 8; ++j)
#pragma unroll
            for (int e = 0; e < 4; ++e) {
                const int h = e >> 1;
                const int r = rb + t * 16 + h * 8 + lq;
                const int col = cb + j * 8 + lr * 2 + (e & 1);
                float v = d[t][j][e] + sm[B2C + col];
                v = (v > 0.0f) ? v : (__expf(v) - 1.0f);
                sm[H1O + r * H1S + col] = v;
            }
    __syncthreads();

    // ---- neighbor-sum -> ss[8][256] -----------------------------------------
    {
        const int b = tid >> 5, c0 = (tid & 31) * 8;
        float4 a0 = make_float4(0.f, 0.f, 0.f, 0.f);
        float4 a1 = make_float4(0.f, 0.f, 0.f, 0.f);
        const float* base = sm + H1O + (b * NEIGH) * H1S + c0;
#pragma unroll
        for (int n = 0; n < NEIGH; ++n) {
            const float4 u0 = *(const float4*)(base + n * H1S);
            const float4 u1 = *(const float4*)(base + n * H1S + 4);
            a0.x += u0.x; a0.y += u0.y; a0.z += u0.z; a0.w += u0.w;
            a1.x += u1.x; a1.y += u1.y; a1.z += u1.z; a1.w += u1.w;
        }
        *(float4*)(sm + SSO + b * H + c0)     = a0;
        *(float4*)(sm + SSO + b * H + c0 + 4) = a1;
    }
    __syncthreads();

    // ---- GEMM3 (SIMT, W3 via LDG/L1): latent = ss @ W3 + b3 -----------------
    {
        const int b = tid >> 5, o = tid & 31;
        const float* ssr = sm + SSO + b * H;
        float a0 = 0.0f, a1 = 0.0f;
#pragma unroll 4
        for (int k = 0; k < H; ++k) {
            const float s = ssr[k];
            a0 = fmaf(s, __ldg(W3 + k * DOUT + o),      a0);
            a1 = fmaf(s, __ldg(W3 + k * DOUT + o + 32), a1);
        }
        float* orow = out + (size_t)(b0 + b) * OUT_DIM + EGO;
        orow[o]      = a0 + sm[B3C + o];
        orow[o + 32] = a1 + sm[B3C + o + 32];
    }
}

extern "C" void kernel_launch(void* const* d_in, const int* in_sizes, int n_in,
                              void* d_out, int out_size)
{
    (void)in_sizes; (void)n_in; (void)out_size;
    const float* obs  = (const float*)d_in[0];
    const float* W1   = (const float*)d_in[1];
    const float* b1   = (const float*)d_in[2];
    const float* ln_g = (const float*)d_in[3];
    const float* ln_b = (const float*)d_in[4];
    const float* W2   = (const float*)d_in[5];
    const float* b2   = (const float*)d_in[6];
    const float* W3   = (const float*)d_in[7];
    const float* b3   = (const float*)d_in[8];
    float* out = (float*)d_out;

    const int prep_elems = (NC1 + NC2) * BUFSZ;
    prep_kernel<<<(prep_elems + 255) / 256, 256>>>(W1, W2);

    cudaFuncSetAttribute(enc3_mma_kernel, cudaFuncAttributeMaxDynamicSharedMemorySize, SMEM_BYTES);
    enc3_mma_kernel<<<BATCHES / BPB, THREADS, SMEM_BYTES>>>(
        obs, b1, ln_g, ln_b, b2, W3, b3, out);
}

// round 15
// speedup vs baseline: 1.6324x; 1.2937x over previous
#include <cuda_runtime.h>
#include <math.h>
#include <stdint.h>

// ===========================================================================
// EncoderAttention3 via mma.sync tf32 (m16n8k8), register accumulators.
// R12: R11 (LDG weights, no mainloop barriers) + GEMM3 on tensor cores
//      (ss kept in kpos fragment layout; W3 pre-laid-out; zero-padded m16)
//      + division-free X assembly. 2 CTAs/SM.
// ===========================================================================

namespace {
constexpr int OBS_DIM = 216, EGO = 48, NEIGH = 7, H = 256, DOUT = 64, OUT_DIM = 112;
constexpr int BATCHES = 16384;
constexpr int BPB     = 8;
constexpr int RVALID  = BPB * NEIGH;   // 56
constexpr int M       = 64;
constexpr int K1      = 80;            // padded 73 -> 80 (5 chunks of 16)
constexpr int THREADS = 256;
constexpr int CH      = 16;
constexpr int NC1     = K1 / CH;       // 5
constexpr int NC2     = H / CH;        // 16
constexpr int XS      = 80;            // X row stride  (320 B; mod 128 == 64)
constexpr int H1S     = 272;           // h1 row stride (1088 B; mod 128 == 64)
constexpr int BUFSZ   = CH * H;        // 4096 floats per 16-k weight chunk [n][16]
constexpr int W3B     = CH * DOUT;     // 1024 floats per 16-k W3 block [n][16]
constexpr int SSS     = 264;           // ss row stride (conflict-free lq dim)

// smem layout (float offsets)
constexpr int B1C = 0;                 // 256
constexpr int GC  = 256;               // 256
constexpr int BBC = 512;               // 256
constexpr int B2C = 768;               // 256
constexpr int B3C = 1024;              // 64
constexpr int PSU = 1088;              // [4][64]
constexpr int PSQ = 1344;              // [4][64]
constexpr int H1O = 1600;              // h1 [64][272]  (X [64][80] aliases this)
constexpr int XO  = H1O;
constexpr int SSO = H1O + M * H1S;     // 19008: ss [8][264] (kpos layout)
constexpr int SMEM_FLOATS = SSO + BPB * SSS;   // 21120
constexpr int SMEM_BYTES  = SMEM_FLOATS * 4;   // 84480 (2 CTAs/SM)
}  // namespace

// weight images, 16-float k-block layout:
//   [n][pos], pos = 4*lr + 2*ks + hh  ->  k = block*16 + ks*8 + lr + 4*hh
__device__ float g_w1[NC1 * BUFSZ];
__device__ float g_w2[NC2 * BUFSZ];
__device__ float g_w3[NC2 * W3B];

// ---------------------------------------------------------------------------
__device__ __forceinline__ uint32_t tf32r(float f) {
    uint32_t u;
    asm("cvt.rna.tf32.f32 %0, %1;" : "=r"(u) : "f"(f));
    return u;
}
__device__ __forceinline__ float tanha(float x) {
    float y;
    asm("tanh.approx.f32 %0, %1;" : "=f"(y) : "f"(x));
    return y;
}
__device__ __forceinline__ void cp16(uint32_t dst, const void* src) {
    asm volatile("cp.async.cg.shared.global [%0], [%1], 16;" :: "r"(dst), "l"(src));
}
#define CP_COMMIT() asm volatile("cp.async.commit_group;" ::: "memory")
#define CP_WAIT0()  asm volatile("cp.async.wait_group 0;" ::: "memory")

__device__ __forceinline__ void mma8(float d[4], const uint32_t a[4],
                                     uint32_t b0, uint32_t b1) {
    asm volatile("mma.sync.aligned.m16n8k8.row.col.f32.tf32.tf32.f32 "
                 "{%0,%1,%2,%3},{%4,%5,%6,%7},{%8,%9},{%0,%1,%2,%3};"
                 : "+f"(d[0]), "+f"(d[1]), "+f"(d[2]), "+f"(d[3])
                 : "r"(a[0]), "r"(a[1]), "r"(a[2]), "r"(a[3]), "r"(b0), "r"(b1));
}

// logical k-in-block (0..15) -> physical position in the 16-float block
__device__ __forceinline__ int kpos(int km) {
    return 4 * (km & 3) + 2 * (km >> 3) + ((km >> 2) & 1);
}

// one 16-k chunk: A (smem, LDS.128, k-block layout), B (global, LDG.128, L1)
__device__ __forceinline__ void gemm_chunk16(const float* __restrict__ A, int as, int k0,
                                             const float4* __restrict__ Bg,
                                             float d[2][8][4], int rb, int cb,
                                             int lq, int lr) {
    uint32_t a[2][2][4];   // [t][ks][frag]
#pragma unroll
    for (int t = 0; t < 2; ++t) {
        const float* ap = A + (rb + t * 16 + lq) * as + k0 + 4 * lr;
        const float4 v0 = *(const float4*)ap;             // row lq
        const float4 v1 = *(const float4*)(ap + 8 * as);  // row lq+8
        a[t][0][0] = __float_as_uint(v0.x); a[t][0][1] = __float_as_uint(v1.x);
        a[t][0][2] = __float_as_uint(v0.y); a[t][0][3] = __float_as_uint(v1.y);
        a[t][1][0] = __float_as_uint(v0.z); a[t][1][1] = __float_as_uint(v1.z);
        a[t][1][2] = __float_as_uint(v0.w); a[t][1][3] = __float_as_uint(v1.w);
    }
    const float4* bb = Bg + (cb + lq) * 4 + lr;
#pragma unroll
    for (int j = 0; j < 8; ++j) {
        const float4 bv = __ldg(bb + j * 32);
        const uint32_t b00 = __float_as_uint(bv.x), b01 = __float_as_uint(bv.y);
        const uint32_t b10 = __float_as_uint(bv.z), b11 = __float_as_uint(bv.w);
        mma8(d[0][j], a[0][0], b00, b01);
        mma8(d[1][j], a[1][0], b00, b01);
        mma8(d[0][j], a[0][1], b10, b11);
        mma8(d[1][j], a[1][1], b10, b11);
    }
}

// ---------------------------------------------------------------------------
__global__ void prep_kernel(const float* __restrict__ W1, const float* __restrict__ W2,
                            const float* __restrict__ W3) {
    const int idx = blockIdx.x * blockDim.x + threadIdx.x;
    const int T1 = NC1 * BUFSZ;
    const int T2 = NC2 * BUFSZ;
    if (idx < T1 + T2) {
        const bool w1 = idx < T1;
        const int i2 = w1 ? idx : idx - T1;
        const int chunk = i2 / BUFSZ;
        const int rem   = i2 - chunk * BUFSZ;
        const int n   = rem >> 4;
        const int pos = rem & 15;
        const int lr = pos >> 2, ks = (pos >> 1) & 1, hh = pos & 1;
        const int k  = chunk * CH + ks * 8 + lr + 4 * hh;
        float v = 0.0f;
        if (w1) { if (k < 73) v = W1[k * H + n]; }
        else                  v = W2[k * H + n];
        (w1 ? g_w1 : g_w2)[i2] = __uint_as_float(tf32r(v));
    } else if (idx < T1 + T2 + NC2 * W3B) {
        const int i3 = idx - T1 - T2;
        const int kb  = i3 >> 10;          // / W3B
        const int rem = i3 & (W3B - 1);
        const int n   = rem >> 4;
        const int pos = rem & 15;
        const int lr = pos >> 2, ks = (pos >> 1) & 1, hh = pos & 1;
        const int k  = kb * CH + ks * 8 + lr + 4 * hh;
        g_w3[i3] = __uint_as_float(tf32r(W3[k * DOUT + n]));
    }
}

// ---------------------------------------------------------------------------
__global__ void __launch_bounds__(THREADS, 2)
enc3_mma_kernel(const float* __restrict__ obs,
                const float* __restrict__ b1, const float* __restrict__ ln_g,
                const float* __restrict__ ln_b, const float* __restrict__ b2,
                const float* __restrict__ b3,
                float* __restrict__ out)
{
    extern __shared__ float sm[];
    const int tid  = threadIdx.x;
    const int wid  = tid >> 5;
    const int lane = tid & 31;
    const int lq   = lane >> 2, lr = lane & 3;
    const int rb   = (wid >> 2) * 32;    // 2 row groups of 32 rows
    const int cb   = (wid & 3) * 64;     // 4 col groups of 64 cols
    const int b0   = blockIdx.x * BPB;
    const uint32_t smu = (uint32_t)__cvta_generic_to_shared(sm);

    // ---- const vectors via cp.async ----------------------------------------
    {
        if (tid < 64)        cp16(smu + B1C * 4 + tid * 16, (const float4*)b1 + tid);
        else if (tid < 128)  cp16(smu + GC  * 4 + (tid - 64) * 16, (const float4*)ln_g + (tid - 64));
        else if (tid < 192)  cp16(smu + BBC * 4 + (tid - 128) * 16, (const float4*)ln_b + (tid - 128));
        else                 cp16(smu + B2C * 4 + (tid - 192) * 16, (const float4*)b2 + (tid - 192));
        if (tid < 16)        cp16(smu + B3C * 4 + tid * 16, (const float4*)b3 + tid);
        CP_COMMIT();
    }

    // ---- assemble X (tf32, k-block layout): 4 threads/row, div-free ---------
    {
        const int r = tid >> 2, sub = tid & 3;
        const int bl = r / NEIGH;
        const int n  = r - bl * NEIGH;
        const float* ob = obs + (size_t)(b0 + bl) * OBS_DIM;
        const bool valid = (r < RVALID);
#pragma unroll
        for (int c = sub * 20; c < sub * 20 + 20; ++c) {
            float v = 0.0f;
            if (valid && c < 73) {
                if (c < EGO)      v = ob[c];
                else if (c < 72)  v = ob[EGO + (c - EGO) * NEIGH + n];
                else              v = (n >= 3) ? 1.0f : 0.0f;
            }
            sm[XO + r * XS + (c & ~15) + kpos(c & 15)] = __uint_as_float(tf32r(v));
        }
    }
    for (int i = tid; i < BPB * EGO; i += THREADS) {
        const int bb = i / EGO, f = i - bb * EGO;
        out[(size_t)(b0 + bb) * OUT_DIM + f] = obs[(size_t)(b0 + bb) * OBS_DIM + f];
    }

    CP_WAIT0();
    __syncthreads();   // X + consts visible block-wide

    float d[2][8][4];
#pragma unroll
    for (int t = 0; t < 2; ++t)
#pragma unroll
        for (int j = 0; j < 8; ++j)
#pragma unroll
            for (int e = 0; e < 4; ++e) d[t][j][e] = 0.0f;

    // ---- GEMM1: 5 chunks, no barriers (B via LDG/L1) ------------------------
#pragma unroll
    for (int c = 0; c < NC1; ++c)
        gemm_chunk16(sm + XO, XS, c * CH, (const float4*)(g_w1 + c * BUFSZ),
                     d, rb, cb, lq, lr);

    // ---- epilogue 1: +b1, LayerNorm, tanh -> h1 (tf32, k-block layout) ------
    {
        float s[2][2] = {{0.f, 0.f}, {0.f, 0.f}};
        float q[2][2] = {{0.f, 0.f}, {0.f, 0.f}};
#pragma unroll
        for (int t = 0; t < 2; ++t)
#pragma unroll
            for (int j = 0; j < 8; ++j)
#pragma unroll
                for (int e = 0; e < 4; ++e) {
                    const float v = d[t][j][e] + sm[B1C + cb + j * 8 + lr * 2 + (e & 1)];
                    d[t][j][e] = v;
                    s[t][e >> 1] += v;
                    q[t][e >> 1] = fmaf(v, v, q[t][e >> 1]);
                }
#pragma unroll
        for (int t = 0; t < 2; ++t)
#pragma unroll
            for (int h = 0; h < 2; ++h)
#pragma unroll
                for (int o = 1; o < 4; o <<= 1) {
                    s[t][h] += __shfl_xor_sync(0xffffffffu, s[t][h], o);
                    q[t][h] += __shfl_xor_sync(0xffffffffu, q[t][h], o);
                }
        if (lr == 0) {
#pragma unroll
            for (int t = 0; t < 2; ++t)
#pragma unroll
                for (int h = 0; h < 2; ++h) {
                    const int r = rb + t * 16 + h * 8 + lq;
                    sm[PSU + (wid & 3) * 64 + r] = s[t][h];
                    sm[PSQ + (wid & 3) * 64 + r] = q[t][h];
                }
        }
        __syncthreads();
        float mu[2][2], rs[2][2];
#pragma unroll
        for (int t = 0; t < 2; ++t)
#pragma unroll
            for (int h = 0; h < 2; ++h) {
                const int r = rb + t * 16 + h * 8 + lq;
                const float ts = sm[PSU + r] + sm[PSU + 64 + r] + sm[PSU + 128 + r] + sm[PSU + 192 + r];
                const float tq = sm[PSQ + r] + sm[PSQ + 64 + r] + sm[PSQ + 128 + r] + sm[PSQ + 192 + r];
                mu[t][h] = ts * (1.0f / 256.0f);
                const float var = fmaf(tq, 1.0f / 256.0f, -mu[t][h] * mu[t][h]);
                rs[t][h] = rsqrtf(var + 1e-5f);
            }
        __syncthreads();   // all warps done reading X before h1 overwrites region
#pragma unroll
        for (int t = 0; t < 2; ++t)
#pragma unroll
            for (int j = 0; j < 8; ++j)
#pragma unroll
                for (int e = 0; e < 4; ++e) {
                    const int h = e >> 1;
                    const int r = rb + t * 16 + h * 8 + lq;
                    const int col = cb + j * 8 + lr * 2 + (e & 1);          // logical
                    const int phys = (col & ~15) + kpos(col & 15);          // k-block
                    const float y = tanha(fmaf((d[t][j][e] - mu[t][h]) * rs[t][h],
                                               sm[GC + col], sm[BBC + col]));
                    sm[H1O + r * H1S + phys] = __uint_as_float(tf32r(y));
                    d[t][j][e] = 0.0f;
                }
    }
    __syncthreads();   // h1 visible block-wide before GEMM2

    // ---- GEMM2: 16 chunks, no barriers (B via LDG/L1) -----------------------
#pragma unroll 4
    for (int c = 0; c < NC2; ++c)
        gemm_chunk16(sm + H1O, H1S, c * CH, (const float4*)(g_w2 + c * BUFSZ),
                     d, rb, cb, lq, lr);
    __syncthreads();   // all warps done reading h1 before epilogue 2 overwrites

    // ---- epilogue 2: +b2, ELU -> h2 (kpos layout, h1 region) ----------------
#pragma unroll
    for (int t = 0; t < 2; ++t)
#pragma unroll
        for (int j = 0; j < 8; ++j)
#pragma unroll
            for (int e = 0; e < 4; ++e) {
                const int h = e >> 1;
                const int r = rb + t * 16 + h * 8 + lq;
                const int col = cb + j * 8 + lr * 2 + (e & 1);
                const int phys = (col & ~15) + kpos(col & 15);
                float v = d[t][j][e] + sm[B2C + col];
                v = (v > 0.0f) ? v : (__expf(v) - 1.0f);
                sm[H1O + r * H1S + phys] = v;
            }
    __syncthreads();

    // ---- neighbor-sum -> ss[8][264] (phys/kpos layout preserved) ------------
    {
        const int b = tid >> 5, c0 = (tid & 31) * 8;
        float4 a0 = make_float4(0.f, 0.f, 0.f, 0.f);
        float4 a1 = make_float4(0.f, 0.f, 0.f, 0.f);
        const float* base = sm + H1O + (b * NEIGH) * H1S + c0;
#pragma unroll
        for (int n = 0; n < NEIGH; ++n) {
            const float4 u0 = *(const float4*)(base + n * H1S);
            const float4 u1 = *(const float4*)(base + n * H1S + 4);
            a0.x += u0.x; a0.y += u0.y; a0.z += u0.z; a0.w += u0.w;
            a1.x += u1.x; a1.y += u1.y; a1.z += u1.z; a1.w += u1.w;
        }
        *(float4*)(sm + SSO + b * SSS + c0)     = a0;
        *(float4*)(sm + SSO + b * SSS + c0 + 4) = a1;
    }
    __syncthreads();

    // ---- GEMM3 via mma: [16(8 valid) x 256] @ W3 -> [8 x 64] ----------------
    {
        float dc[4] = {0.f, 0.f, 0.f, 0.f};
        const float*  ssr = sm + SSO + lq * SSS + lr * 4;
        const float4* w3p = (const float4*)(g_w3 + (wid * 8 + lq) * 16 + lr * 4);
#pragma unroll
        for (int kb = 0; kb < NC2; ++kb) {
            const float4 av = *(const float4*)(ssr + kb * 16);
            const float4 bv = __ldg(w3p + kb * (W3B / 4));
            const uint32_t a0[4] = {tf32r(av.x), 0u, tf32r(av.y), 0u};
            const uint32_t a1[4] = {tf32r(av.z), 0u, tf32r(av.w), 0u};
            mma8(dc, a0, __float_as_uint(bv.x), __float_as_uint(bv.y));
            mma8(dc, a1, __float_as_uint(bv.z), __float_as_uint(bv.w));
        }
        const int oc = wid * 8 + 2 * lr;
        float* orow = out + (size_t)(b0 + lq) * OUT_DIM + EGO + oc;
        orow[0] = dc[0] + sm[B3C + oc];
        orow[1] = dc[1] + sm[B3C + oc + 1];
    }
}

extern "C" void kernel_launch(void* const* d_in, const int* in_sizes, int n_in,
                              void* d_out, int out_size)
{
    (void)in_sizes; (void)n_in; (void)out_size;
    const float* obs  = (const float*)d_in[0];
    const float* W1   = (const float*)d_in[1];
    const float* b1   = (const float*)d_in[2];
    const float* ln_g = (const float*)d_in[3];
    const float* ln_b = (const float*)d_in[4];
    const float* W2   = (const float*)d_in[5];
    const float* b2   = (const float*)d_in[6];
    const float* W3   = (const float*)d_in[7];
    const float* b3   = (const float*)d_in[8];
    float* out = (float*)d_out;

    const int prep_elems = (NC1 + NC2) * BUFSZ + NC2 * W3B;
    prep_kernel<<<(prep_elems + 255) / 256, 256>>>(W1, W2, W3);

    cudaFuncSetAttribute(enc3_mma_kernel, cudaFuncAttributeMaxDynamicSharedMemorySize, SMEM_BYTES);
    enc3_mma_kernel<<<BATCHES / BPB, THREADS, SMEM_BYTES>>>(
        obs, b1, ln_g, ln_b, b2, b3, out);
}